// round 14
// baseline (speedup 1.0000x reference)
#include <cuda_runtime.h>
#include <cuda_bf16.h>
#include <cstdint>

#define B_   256
#define H_   6
#define NT   343
#define NTP  344
#define DH   32
#define C_   192
#define NWIN 32
#define M_   (B_*NT)          // 87808
#define KS2  33               // attn k/v smem row stride (floats)

#if defined(__CUDA_ARCH_FEAT_SM103_ALL) || \
    (defined(__CUDA_ARCH_SPECIFIC__) && (__CUDA_ARCH_SPECIFIC__ == 1030))
#define HAS_TCGEN05 1
#else
#define HAS_TCGEN05 0
#endif

// Scratch (static device allocations — allowed)
__device__ __align__(16) float g_k[(size_t)B_*H_*NT*DH];
__device__ __align__(16) float g_v[(size_t)B_*H_*NT*DH];
__device__ __align__(16) float g_x[(size_t)B_*NT*C_];
__device__ __align__(16) float g_bias[(size_t)H_*NT*NT];
// transposed + split weights (bf16 hi/lo):  Wt[n][k]
__device__ __align__(16) __nv_bfloat16 g_wh[384*192];
__device__ __align__(16) __nv_bfloat16 g_wl[384*192];
__device__ __align__(16) __nv_bfloat16 g_ph[192*192];
__device__ __align__(16) __nv_bfloat16 g_pl[192*192];

// ============================ PTX helpers ==================================
__device__ __forceinline__ uint32_t smem_u32(const void* p) {
    uint32_t a;
    asm("{ .reg .u64 t; cvta.to.shared.u64 t, %1; cvt.u32.u64 %0, t; }"
        : "=r"(a) : "l"(p));
    return a;
}

#if HAS_TCGEN05
__device__ __forceinline__ uint32_t elect_one() {
    uint32_t p;
    asm volatile("{ .reg .pred p; elect.sync _|p, 0xFFFFFFFF; selp.b32 %0,1,0,p; }"
                 : "=r"(p));
    return p;
}
#define TC_ALLOC(sm, n)  asm volatile("tcgen05.alloc.cta_group::1.sync.aligned.shared::cta.b32 [%0], %1;" :: "r"(sm), "r"(n) : "memory")
#define TC_RELINQ()      asm volatile("tcgen05.relinquish_alloc_permit.cta_group::1.sync.aligned;")
#define TC_DEALLOC(t, n) asm volatile("tcgen05.dealloc.cta_group::1.sync.aligned.b32 %0, %1;" :: "r"(t), "r"(n))
#define TC_COMMIT(mb)    asm volatile("tcgen05.commit.cta_group::1.mbarrier::arrive::one.shared::cluster.b64 [%0];" :: "r"(mb) : "memory")
#define TC_FENCE_AFTER() asm volatile("tcgen05.fence::after_thread_sync;" ::: "memory")
#define TC_WAIT_LD()     asm volatile("tcgen05.wait::ld.sync.aligned;" ::: "memory")
#define FENCE_ASYNC()    asm volatile("fence.proxy.async.shared::cta;" ::: "memory")
#define MBAR_INIT(mb, c) asm volatile("mbarrier.init.shared.b64 [%0], %1;" :: "r"(mb), "r"(c) : "memory")
#define MBAR_WAIT(mb, ph) do {                                                    \
    asm volatile("{ .reg .pred P1; WL%=:\n\t"                                     \
        "mbarrier.try_wait.parity.acquire.cta.shared::cta.b64 P1, [%0], %1, 0x989680;\n\t" \
        "@P1 bra.uni WD%=;\n\t bra.uni WL%=;\n\t WD%=: }"                          \
        :: "r"(mb), "r"(ph) : "memory");                                           \
} while (0)
#define TC_LD32X32(r, ta)                                                          \
    asm volatile("tcgen05.ld.sync.aligned.32x32b.x32.b32 "                         \
        "{%0,%1,%2,%3,%4,%5,%6,%7,%8,%9,%10,%11,%12,%13,%14,%15,"                  \
        "%16,%17,%18,%19,%20,%21,%22,%23,%24,%25,%26,%27,%28,%29,%30,%31}, [%32];" \
        : "=r"((r)[0]),"=r"((r)[1]),"=r"((r)[2]),"=r"((r)[3]),                     \
          "=r"((r)[4]),"=r"((r)[5]),"=r"((r)[6]),"=r"((r)[7]),                     \
          "=r"((r)[8]),"=r"((r)[9]),"=r"((r)[10]),"=r"((r)[11]),                   \
          "=r"((r)[12]),"=r"((r)[13]),"=r"((r)[14]),"=r"((r)[15]),                 \
          "=r"((r)[16]),"=r"((r)[17]),"=r"((r)[18]),"=r"((r)[19]),                 \
          "=r"((r)[20]),"=r"((r)[21]),"=r"((r)[22]),"=r"((r)[23]),                 \
          "=r"((r)[24]),"=r"((r)[25]),"=r"((r)[26]),"=r"((r)[27]),                 \
          "=r"((r)[28]),"=r"((r)[29]),"=r"((r)[30]),"=r"((r)[31])                  \
        : "r"(ta))

__device__ __forceinline__ void mma_f16_ss(uint32_t d, uint64_t ad, uint64_t bd,
                                           uint32_t idesc, uint32_t en) {
    asm volatile("{ .reg .pred p; setp.ne.u32 p, %5, 0;\n\t"
        "tcgen05.mma.cta_group::1.kind::f16 [%0], %1, %2, %3, {%4,%4,%4,%4}, p; }"
        :: "r"(d), "l"(ad), "l"(bd), "r"(idesc), "r"(0u), "r"(en) : "memory");
}

// SW128 smem descriptor base: layout=2(SW128), version=1, SBO=64, LBO=1
__device__ __forceinline__ uint64_t mk_desc(uint32_t addr) {
    return ((uint64_t)2 << 61) | ((uint64_t)1 << 46) | ((uint64_t)64 << 32) |
           ((uint64_t)1 << 16) | ((uint64_t)(addr >> 4) & 0x3FFF);
}
#endif  // HAS_TCGEN05

#define SWZ(x) ((x) ^ (((x) >> 3) & 0x70))

__device__ __forceinline__ void bsplit(float x, unsigned short& h, unsigned short& l) {
    __nv_bfloat16 bh = __float2bfloat16(x);
    __nv_bfloat16 bl = __float2bfloat16(x - __bfloat162float(bh));
    h = __bfloat16_as_ushort(bh);
    l = __bfloat16_as_ushort(bl);
}

// idesc: F32 acc, BF16 a/b, N=64, M=128
#define IDESC ((1u<<4) | (1u<<7) | (1u<<10) | ((64u/8)<<17) | ((128u/16)<<24))

// ---------------------------------------------------------------------------
// Kernel 0: transpose + split W (fp32 [192][ncol] -> bf16 hi/lo [ncol][192])
// ---------------------------------------------------------------------------
__global__ void wconv_kernel(const float* __restrict__ W, int ncol,
                             __nv_bfloat16* __restrict__ Th,
                             __nv_bfloat16* __restrict__ Tl) {
    int idx = blockIdx.x * 256 + threadIdx.x;
    if (idx < 192 * ncol) {
        int n = idx / 192, k = idx - n * 192;
        float x = W[(size_t)k * ncol + n];
        unsigned short h, l;
        bsplit(x, h, l);
        Th[idx] = __ushort_as_bfloat16(h);
        Tl[idx] = __ushort_as_bfloat16(l);
    }
}

// ---------------------------------------------------------------------------
// Kernel 1: gather relative-position bias
// ---------------------------------------------------------------------------
__global__ void bias_gather_kernel(const int* __restrict__ rel,
                                   const float* __restrict__ table,
                                   float* __restrict__ bias) {
    int idx = blockIdx.x * 256 + threadIdx.x;
    if (idx < NT * NT) {
        int r = rel[idx];
        #pragma unroll
        for (int h = 0; h < H_; h++)
            bias[(size_t)h * (NT * NT) + idx] = table[r * H_ + h];
    }
}

// ---------------------------------------------------------------------------
// tcgen05 bf16 split GEMM, N-looped + pipelined:
//   One CTA per 128-row M-block. A (hi/lo) staged once; loop over NB N-blocks
//   of 64 cols with double-buffered W and alternating 64-col TMEM D regions.
//   MMA n+1 issued before epilogue n -> tensor overlaps LDTM/stores.
// MODE 0: scatter kv -> out0(g_k)/out1(g_v);  MODE 1: row-major out0.
// ---------------------------------------------------------------------------
#define OFF_AH 1024
#define OFF_AL (OFF_AH + 128*192*2)        // 50176
#define OFF_W(buf, hl) (OFF_AL + 128*192*2 + ((buf)*2 + (hl)) * 64*192*2)
#define SMEM_GEMM (OFF_W(1,1) + 64*192*2 + 1024)   // ~198656

template <int NCOL, int MODE>
__device__ __forceinline__ void gemm_store(int row, int col, float val,
                                           float* out0, float* out1) {
    int b = row / NT, nn = row - b * NT;
    if (MODE == 0) {
        int p   = col / 192;
        int rem = col - p * 192;
        int h   = rem >> 5;
        int d   = rem & 31;
        float* dst = p ? out1 : out0;
        dst[((size_t)(b * H_ + h) * NT + nn) * DH + d] = val;
    } else {
        out0[(size_t)row * NCOL + col] = val;
    }
}

#if HAS_TCGEN05
__device__ __forceinline__ void stage_w(char* alg, int buf,
                                        const __nv_bfloat16* Wh,
                                        const __nv_bfloat16* Wl,
                                        int n0, int tid) {
    const __nv_bfloat16* wh = Wh + (size_t)n0 * 192;
    const __nv_bfloat16* wl = Wl + (size_t)n0 * 192;
    for (int id = tid; id < 64 * 24; id += 256) {
        int row = id / 24;
        int col = (id - row * 24) * 8;
        uint32_t off = (uint32_t)(((row >> 3) + (col >> 6) * 8) * 1024 +
                                  (row & 7) * 128 + (col & 63) * 2);
        uint32_t sw = SWZ(off);
        *(uint4*)(alg + OFF_W(buf, 0) + sw) = *(const uint4*)(wh + (size_t)row * 192 + col);
        *(uint4*)(alg + OFF_W(buf, 1) + sw) = *(const uint4*)(wl + (size_t)row * 192 + col);
    }
}

__device__ __forceinline__ void issue_mma_block(uint32_t base, uint32_t tmem_d,
                                                int buf) {
    uint64_t dAh = mk_desc(base + OFF_AH);
    uint64_t dAl = mk_desc(base + OFF_AL);
    uint64_t dWh = mk_desc(base + OFF_W(buf, 0));
    uint64_t dWl = mk_desc(base + OFF_W(buf, 1));
    uint64_t aB[3] = {dAh, dAl, dAh};
    uint64_t bB[3] = {dWh, dWh, dWl};
    #pragma unroll
    for (int t = 0; t < 3; t++) {
        #pragma unroll
        for (int s = 0; s < 12; s++) {
            uint64_t ad = aB[t] + (uint64_t)((s >> 2) * 1024 + (s & 3) * 2);
            uint64_t bd = bB[t] + (uint64_t)((s >> 2) * 512  + (s & 3) * 2);
            mma_f16_ss(tmem_d, ad, bd, IDESC, (t | s) != 0);
        }
    }
    TC_COMMIT(base + 8);
}
#endif

template <int NCOL, int MODE>
__global__ __launch_bounds__(256, 1)
void mma_gemm_kernel(const float* __restrict__ A,
                     const __nv_bfloat16* __restrict__ Wh,
                     const __nv_bfloat16* __restrict__ Wl,
                     const float* __restrict__ bias,
                     float* __restrict__ out0,
                     float* __restrict__ out1) {
#if HAS_TCGEN05
    constexpr int NB = NCOL / 64;
    extern __shared__ char smx[];
    const uint32_t raw = smem_u32(smx);
    const uint32_t base = (raw + 1023) & ~1023u;          // 1KB-aligned
    char* alg = smx + (base - raw);

    const int tid = threadIdx.x;
    const int wid = tid >> 5, lid = tid & 31;
    const int M0 = blockIdx.x * 128;

    if (wid == 0) {
        TC_ALLOC(base, 128);
        TC_RELINQ();
    }
    if (tid == 0) MBAR_INIT(base + 8, 1);

    // ---- stage A tile once: fp32 -> (hi, lo) bf16, SW128 blocked atoms ----
    for (int id = tid; id < 128 * 48; id += 256) {
        int row = id / 48;
        int col = (id - row * 48) * 4;
        float4 a = *(const float4*)(A + (size_t)(M0 + row) * 192 + col);
        unsigned short h0,h1,h2,h3,l0,l1,l2,l3;
        bsplit(a.x, h0, l0); bsplit(a.y, h1, l1);
        bsplit(a.z, h2, l2); bsplit(a.w, h3, l3);
        uint32_t off = (uint32_t)(((row >> 3) + (col >> 6) * 16) * 1024 +
                                  (row & 7) * 128 + (col & 63) * 2);
        uint32_t sw = SWZ(off);
        *(uint2*)(alg + OFF_AH + sw) =
            make_uint2((uint32_t)h0 | ((uint32_t)h1 << 16),
                       (uint32_t)h2 | ((uint32_t)h3 << 16));
        *(uint2*)(alg + OFF_AL + sw) =
            make_uint2((uint32_t)l0 | ((uint32_t)l1 << 16),
                       (uint32_t)l2 | ((uint32_t)l3 << 16));
    }
    // ---- stage W block 0 ----
    stage_w(alg, 0, Wh, Wl, 0, tid);
    FENCE_ASYNC();
    __syncthreads();

    uint32_t tmem;
    asm volatile("ld.shared.b32 %0, [%1];" : "=r"(tmem) : "r"(base));

    // ---- issue MMA block 0 ----
    if (wid == 0 && elect_one())
        issue_mma_block(base, tmem + 0, 0);

    // ---- pipelined N-block loop ----
    for (int n = 0; n < NB; n++) {
        if (n + 1 < NB)
            stage_w(alg, (n + 1) & 1, Wh, Wl, (n + 1) * 64, tid);
        FENCE_ASYNC();
        __syncthreads();

        MBAR_WAIT(base + 8, n & 1);          // MMA block n done
        TC_FENCE_AFTER();

        if (n + 1 < NB && wid == 0 && elect_one())
            issue_mma_block(base, tmem + ((n + 1) & 1) * 64, (n + 1) & 1);

        // epilogue block n: warps 0-3 read D[128,64] region (n&1)
        if (wid < 4) {
            uint32_t d0[32], d1[32];
            uint32_t td = tmem + (n & 1) * 64;
            TC_LD32X32(d0, td);
            TC_LD32X32(d1, td + 32);
            TC_WAIT_LD();
            int row = M0 + wid * 32 + lid;
            int N0 = n * 64;
            #pragma unroll
            for (int c = 0; c < 64; c++) {
                int col = N0 + c;
                float val = __uint_as_float(c < 32 ? d0[c] : d1[c - 32]) + bias[col];
                gemm_store<NCOL, MODE>(row, col, val, out0, out1);
            }
        }
    }

    __syncthreads();
    if (wid == 0) TC_DEALLOC(tmem, 128);

#else
    // ---------- SIMT fallback (compiled for non-a targets only) ----------
    const int tid = threadIdx.x;
    const int M0 = blockIdx.x * 128;
    int row = M0 + (tid >> 1);
    int half = (tid & 1);
    for (int nb = 0; nb < NCOL / 64; nb++) {
        int c0 = nb * 64 + half * 32;
        float acc[32];
        #pragma unroll
        for (int j = 0; j < 32; j++) acc[j] = 0.f;
        for (int k = 0; k < 192; k++) {
            float a = A[(size_t)row * 192 + k];
            #pragma unroll 8
            for (int j = 0; j < 32; j++) {
                float w = __bfloat162float(Wh[(size_t)(c0 + j) * 192 + k]) +
                          __bfloat162float(Wl[(size_t)(c0 + j) * 192 + k]);
                acc[j] += a * w;
            }
        }
        #pragma unroll
        for (int j = 0; j < 32; j++)
            gemm_store<NCOL, MODE>(row, c0 + j, acc[j] + bias[c0 + j], out0, out1);
    }
#endif
}

// ---------------------------------------------------------------------------
// Kernel 3: fused window attention (unchanged — known good)
// ---------------------------------------------------------------------------
__global__ __launch_bounds__(512, 1)
void attn_kernel(const float* __restrict__ xup,
                 const float* __restrict__ gk,
                 const float* __restrict__ gv,
                 const float* __restrict__ bias,
                 const float* __restrict__ mask,
                 float* __restrict__ xout) {
    extern __shared__ float sm[];
    float* ks = sm;                         // 344 * 33
    float* vs = ks + NTP * KS2;             // 344 * 33
    float* qs = vs + NTP * KS2;             // 16 * 128
    float* ps = qs + 16 * 128;              // 16 * 4 * 344

    const int tid = threadIdx.x;
    const int bh  = blockIdx.x;             // b*6 + h
    const int b   = bh / H_;
    const int h   = bh - b * H_;
    const int w   = b & (NWIN - 1);

    const float4* kg = (const float4*)(gk + (size_t)bh * NT * DH);
    const float4* vg = (const float4*)(gv + (size_t)bh * NT * DH);
    for (int idx = tid; idx < NT * 8; idx += 512) {
        int j = idx >> 3, c = (idx & 7) << 2;
        float4 a4 = kg[idx];
        float* kd = ks + j * KS2 + c;
        kd[0] = a4.x; kd[1] = a4.y; kd[2] = a4.z; kd[3] = a4.w;
        float4 b4 = vg[idx];
        float* vd = vs + j * KS2 + c;
        vd[0] = b4.x; vd[1] = b4.y; vd[2] = b4.z; vd[3] = b4.w;
    }
    if (tid < KS2) {
        ks[343 * KS2 + tid] = 0.f;
        vs[343 * KS2 + tid] = 0.f;
    }
    __syncthreads();

    const int warp = tid >> 5, lane = tid & 31;
    const float scale = 0.17677669529663687f;
    float* qw = qs + warp * 128;
    float* pw = ps + warp * 4 * NTP;
    const float* brow0 = bias + (size_t)h * NT * NT;
    const float* mrow0 = mask + (size_t)w * NT * NT;

    for (int it = 0; it < 6; it++) {
        const int row0 = it * 64 + warp * 4;

        #pragma unroll
        for (int rr = 0; rr < 4; rr++) {
            int row = min(row0 + rr, NT - 1);
            qw[rr * 32 + lane] =
                xup[((size_t)b * NT + row) * C_ + h * DH + lane] * scale;
        }
        __syncwarp();

        float acc[4][11];
        #pragma unroll
        for (int r = 0; r < 4; r++)
            #pragma unroll
            for (int tt = 0; tt < 11; tt++) acc[r][tt] = 0.f;

        #pragma unroll
        for (int dc = 0; dc < 32; dc += 8) {
            float qr[4][8];
            #pragma unroll
            for (int r = 0; r < 4; r++)
                #pragma unroll
                for (int dd = 0; dd < 8; dd++)
                    qr[r][dd] = qw[r * 32 + dc + dd];
            #pragma unroll
            for (int tt = 0; tt < 11; tt++) {
                int j  = tt * 32 + lane;
                int jc = min(j, NT);
                const float* kp = ks + jc * KS2 + dc;
                #pragma unroll
                for (int dd = 0; dd < 8; dd++) {
                    float kv = kp[dd];
                    #pragma unroll
                    for (int r = 0; r < 4; r++)
                        acc[r][tt] += qr[r][dd] * kv;
                }
            }
        }

        #pragma unroll
        for (int r = 0; r < 4; r++) {
            int row = min(row0 + r, NT - 1);
            const float* br = brow0 + (size_t)row * NT;
            const float* mr = mrow0 + (size_t)row * NT;
            float sreg[11];
            float mx = -1e30f;
            #pragma unroll
            for (int tt = 0; tt < 11; tt++) {
                int j = tt * 32 + lane;
                float s = -1e30f;
                if (j < NT) s = acc[r][tt] + br[j] + mr[j];
                sreg[tt] = s;
                mx = fmaxf(mx, s);
            }
            #pragma unroll
            for (int o = 16; o > 0; o >>= 1)
                mx = fmaxf(mx, __shfl_xor_sync(0xffffffffu, mx, o));
            float sum = 0.f;
            #pragma unroll
            for (int tt = 0; tt < 11; tt++) {
                float e = __expf(sreg[tt] - mx);
                sreg[tt] = e;
                sum += e;
            }
            #pragma unroll
            for (int o = 16; o > 0; o >>= 1)
                sum += __shfl_xor_sync(0xffffffffu, sum, o);
            float inv = 1.f / sum;
            #pragma unroll
            for (int tt = 0; tt < 11; tt++) {
                int j = tt * 32 + lane;
                if (j < NT) pw[r * NTP + j] = sreg[tt] * inv;
            }
            if (lane == 0) pw[r * NTP + NT] = 0.f;
        }
        __syncwarp();

        float o0 = 0.f, o1 = 0.f, o2 = 0.f, o3 = 0.f;
        #pragma unroll 2
        for (int j4 = 0; j4 < NTP; j4 += 4) {
            float vv0 = vs[(j4 + 0) * KS2 + lane];
            float vv1 = vs[(j4 + 1) * KS2 + lane];
            float vv2 = vs[(j4 + 2) * KS2 + lane];
            float vv3 = vs[(j4 + 3) * KS2 + lane];
            float4 p0 = *(const float4*)&pw[0 * NTP + j4];
            float4 p1 = *(const float4*)&pw[1 * NTP + j4];
            float4 p2 = *(const float4*)&pw[2 * NTP + j4];
            float4 p3 = *(const float4*)&pw[3 * NTP + j4];
            o0 += p0.x * vv0 + p0.y * vv1 + p0.z * vv2 + p0.w * vv3;
            o1 += p1.x * vv0 + p1.y * vv1 + p1.z * vv2 + p1.w * vv3;
            o2 += p2.x * vv0 + p2.y * vv1 + p2.z * vv2 + p2.w * vv3;
            o3 += p3.x * vv0 + p3.y * vv1 + p3.z * vv2 + p3.w * vv3;
        }

        float ov[4] = {o0, o1, o2, o3};
        #pragma unroll
        for (int r = 0; r < 4; r++) {
            int row = row0 + r;
            if (row < NT)
                xout[((size_t)b * NT + row) * C_ + h * DH + lane] = ov[r];
        }
        __syncwarp();
    }
}

// ---------------------------------------------------------------------------
extern "C" void kernel_launch(void* const* d_in, const int* in_sizes, int n_in,
                              void* d_out, int out_size) {
    const float* skip   = (const float*)d_in[0];
    const float* x_up   = (const float*)d_in[1];
    const float* mask   = (const float*)d_in[2];
    const int*   rel    = (const int*)d_in[3];
    const float* table  = (const float*)d_in[4];
    const float* kv_w   = (const float*)d_in[5];
    const float* kv_b   = (const float*)d_in[6];
    const float* proj_w = (const float*)d_in[7];
    const float* proj_b = (const float*)d_in[8];
    float* out = (float*)d_out;

    float *kptr, *vptr, *xptr, *biasptr;
    __nv_bfloat16 *whp, *wlp, *php, *plp;
    cudaGetSymbolAddress((void**)&kptr, g_k);
    cudaGetSymbolAddress((void**)&vptr, g_v);
    cudaGetSymbolAddress((void**)&xptr, g_x);
    cudaGetSymbolAddress((void**)&biasptr, g_bias);
    cudaGetSymbolAddress((void**)&whp, g_wh);
    cudaGetSymbolAddress((void**)&wlp, g_wl);
    cudaGetSymbolAddress((void**)&php, g_ph);
    cudaGetSymbolAddress((void**)&plp, g_pl);

    // 0. weight transpose + split
    wconv_kernel<<<(384 * 192 + 255) / 256, 256>>>(kv_w, 384, whp, wlp);
    wconv_kernel<<<(192 * 192 + 255) / 256, 256>>>(proj_w, 192, php, plp);

    // 1. bias gather
    bias_gather_kernel<<<(NT * NT + 255) / 256, 256>>>(rel, table, biasptr);

    // 2. kv projection (tcgen05, N-looped, scatter to g_k/g_v)
    cudaFuncSetAttribute(mma_gemm_kernel<384, 0>,
                         cudaFuncAttributeMaxDynamicSharedMemorySize, SMEM_GEMM);
    mma_gemm_kernel<384, 0><<<M_ / 128, 256, SMEM_GEMM>>>(
        skip, whp, wlp, kv_b, kptr, vptr);

    // 3. fused attention
    const int SMEM_ATTN = (2 * NTP * KS2 + 16 * 128 + 16 * 4 * NTP) * (int)sizeof(float);
    cudaFuncSetAttribute(attn_kernel, cudaFuncAttributeMaxDynamicSharedMemorySize, SMEM_ATTN);
    attn_kernel<<<B_ * H_, 512, SMEM_ATTN>>>(x_up, kptr, vptr, biasptr, mask, xptr);

    // 4. output projection (tcgen05) straight to d_out
    cudaFuncSetAttribute(mma_gemm_kernel<192, 1>,
                         cudaFuncAttributeMaxDynamicSharedMemorySize, SMEM_GEMM);
    mma_gemm_kernel<192, 1><<<M_ / 128, 256, SMEM_GEMM>>>(
        xptr, php, plp, proj_b, out, nullptr);
}

// round 15
// speedup vs baseline: 1.0040x; 1.0040x over previous
#include <cuda_runtime.h>
#include <cuda_bf16.h>
#include <cstdint>

#define B_   256
#define H_   6
#define NT   343
#define NTP  344
#define DH   32
#define C_   192
#define NWIN 32
#define M_   (B_*NT)          // 87808
#define KS2  33               // attn k/v smem row stride (floats)

#if defined(__CUDA_ARCH_FEAT_SM103_ALL) || \
    (defined(__CUDA_ARCH_SPECIFIC__) && (__CUDA_ARCH_SPECIFIC__ == 1030))
#define HAS_TCGEN05 1
#else
#define HAS_TCGEN05 0
#endif

// Scratch (static device allocations — allowed)
__device__ __align__(16) float g_k[(size_t)B_*H_*NT*DH];
__device__ __align__(16) float g_v[(size_t)B_*H_*NT*DH];
__device__ __align__(16) float g_x[(size_t)B_*NT*C_];
__device__ __align__(16) float g_bias[(size_t)H_*NT*NT];
// transposed + split weights (bf16 hi/lo):  Wt[n][k]
__device__ __align__(16) __nv_bfloat16 g_wh[384*192];
__device__ __align__(16) __nv_bfloat16 g_wl[384*192];
__device__ __align__(16) __nv_bfloat16 g_ph[192*192];
__device__ __align__(16) __nv_bfloat16 g_pl[192*192];

// ============================ PTX helpers ==================================
__device__ __forceinline__ uint32_t smem_u32(const void* p) {
    uint32_t a;
    asm("{ .reg .u64 t; cvta.to.shared.u64 t, %1; cvt.u32.u64 %0, t; }"
        : "=r"(a) : "l"(p));
    return a;
}

#if HAS_TCGEN05
__device__ __forceinline__ uint32_t elect_one() {
    uint32_t p;
    asm volatile("{ .reg .pred p; elect.sync _|p, 0xFFFFFFFF; selp.b32 %0,1,0,p; }"
                 : "=r"(p));
    return p;
}
#define TC_ALLOC(sm, n)  asm volatile("tcgen05.alloc.cta_group::1.sync.aligned.shared::cta.b32 [%0], %1;" :: "r"(sm), "r"(n) : "memory")
#define TC_RELINQ()      asm volatile("tcgen05.relinquish_alloc_permit.cta_group::1.sync.aligned;")
#define TC_DEALLOC(t, n) asm volatile("tcgen05.dealloc.cta_group::1.sync.aligned.b32 %0, %1;" :: "r"(t), "r"(n))
#define TC_COMMIT(mb)    asm volatile("tcgen05.commit.cta_group::1.mbarrier::arrive::one.shared::cluster.b64 [%0];" :: "r"(mb) : "memory")
#define TC_FENCE_AFTER() asm volatile("tcgen05.fence::after_thread_sync;" ::: "memory")
#define TC_WAIT_LD()     asm volatile("tcgen05.wait::ld.sync.aligned;" ::: "memory")
#define FENCE_ASYNC()    asm volatile("fence.proxy.async.shared::cta;" ::: "memory")
#define MBAR_INIT(mb, c) asm volatile("mbarrier.init.shared.b64 [%0], %1;" :: "r"(mb), "r"(c) : "memory")
#define MBAR_WAIT(mb, ph) do {                                                    \
    asm volatile("{ .reg .pred P1; WL%=:\n\t"                                     \
        "mbarrier.try_wait.parity.acquire.cta.shared::cta.b64 P1, [%0], %1, 0x989680;\n\t" \
        "@P1 bra.uni WD%=;\n\t bra.uni WL%=;\n\t WD%=: }"                          \
        :: "r"(mb), "r"(ph) : "memory");                                           \
} while (0)
#define TC_LD32X32(r, ta)                                                          \
    asm volatile("tcgen05.ld.sync.aligned.32x32b.x32.b32 "                         \
        "{%0,%1,%2,%3,%4,%5,%6,%7,%8,%9,%10,%11,%12,%13,%14,%15,"                  \
        "%16,%17,%18,%19,%20,%21,%22,%23,%24,%25,%26,%27,%28,%29,%30,%31}, [%32];" \
        : "=r"((r)[0]),"=r"((r)[1]),"=r"((r)[2]),"=r"((r)[3]),                     \
          "=r"((r)[4]),"=r"((r)[5]),"=r"((r)[6]),"=r"((r)[7]),                     \
          "=r"((r)[8]),"=r"((r)[9]),"=r"((r)[10]),"=r"((r)[11]),                   \
          "=r"((r)[12]),"=r"((r)[13]),"=r"((r)[14]),"=r"((r)[15]),                 \
          "=r"((r)[16]),"=r"((r)[17]),"=r"((r)[18]),"=r"((r)[19]),                 \
          "=r"((r)[20]),"=r"((r)[21]),"=r"((r)[22]),"=r"((r)[23]),                 \
          "=r"((r)[24]),"=r"((r)[25]),"=r"((r)[26]),"=r"((r)[27]),                 \
          "=r"((r)[28]),"=r"((r)[29]),"=r"((r)[30]),"=r"((r)[31])                  \
        : "r"(ta))

__device__ __forceinline__ void mma_f16_ss(uint32_t d, uint64_t ad, uint64_t bd,
                                           uint32_t idesc, uint32_t en) {
    asm volatile("{ .reg .pred p; setp.ne.u32 p, %5, 0;\n\t"
        "tcgen05.mma.cta_group::1.kind::f16 [%0], %1, %2, %3, {%4,%4,%4,%4}, p; }"
        :: "r"(d), "l"(ad), "l"(bd), "r"(idesc), "r"(0u), "r"(en) : "memory");
}

// SW128 smem descriptor base: layout=2(SW128), version=1, SBO=64, LBO=1
__device__ __forceinline__ uint64_t mk_desc(uint32_t addr) {
    return ((uint64_t)2 << 61) | ((uint64_t)1 << 46) | ((uint64_t)64 << 32) |
           ((uint64_t)1 << 16) | ((uint64_t)(addr >> 4) & 0x3FFF);
}
#endif  // HAS_TCGEN05

#define SWZ(x) ((x) ^ (((x) >> 3) & 0x70))

__device__ __forceinline__ void bsplit(float x, unsigned short& h, unsigned short& l) {
    __nv_bfloat16 bh = __float2bfloat16(x);
    __nv_bfloat16 bl = __float2bfloat16(x - __bfloat162float(bh));
    h = __bfloat16_as_ushort(bh);
    l = __bfloat16_as_ushort(bl);
}

// idesc: F32 acc, BF16 a/b, N=64, M=128
#define IDESC ((1u<<4) | (1u<<7) | (1u<<10) | ((64u/8)<<17) | ((128u/16)<<24))

// ---------------------------------------------------------------------------
// Kernel 0: transpose + split W (fp32 [192][ncol] -> bf16 hi/lo [ncol][192])
// ---------------------------------------------------------------------------
__global__ void wconv_kernel(const float* __restrict__ W, int ncol,
                             __nv_bfloat16* __restrict__ Th,
                             __nv_bfloat16* __restrict__ Tl) {
    int idx = blockIdx.x * 256 + threadIdx.x;
    if (idx < 192 * ncol) {
        int n = idx / 192, k = idx - n * 192;
        float x = W[(size_t)k * ncol + n];
        unsigned short h, l;
        bsplit(x, h, l);
        Th[idx] = __ushort_as_bfloat16(h);
        Tl[idx] = __ushort_as_bfloat16(l);
    }
}

// ---------------------------------------------------------------------------
// Kernel 1: gather relative-position bias
// ---------------------------------------------------------------------------
__global__ void bias_gather_kernel(const int* __restrict__ rel,
                                   const float* __restrict__ table,
                                   float* __restrict__ bias) {
    int idx = blockIdx.x * 256 + threadIdx.x;
    if (idx < NT * NT) {
        int r = rel[idx];
        #pragma unroll
        for (int h = 0; h < H_; h++)
            bias[(size_t)h * (NT * NT) + idx] = table[r * H_ + h];
    }
}

// ---------------------------------------------------------------------------
// tcgen05 bf16 split GEMM, N-looped + pipelined:
//   One CTA per 128-row M-block. A (hi/lo) staged once; loop over NB N-blocks
//   of 64 cols with double-buffered W and alternating 64-col TMEM D regions.
//   MMA n+1 issued before epilogue n -> tensor overlaps LDTM/stores.
// MODE 0: scatter kv -> out0(g_k)/out1(g_v);  MODE 1: row-major out0.
// ---------------------------------------------------------------------------
#define OFF_AH 1024
#define OFF_AL (OFF_AH + 128*192*2)        // 50176
#define OFF_W(buf, hl) (OFF_AL + 128*192*2 + ((buf)*2 + (hl)) * 64*192*2)
#define SMEM_GEMM (OFF_W(1,1) + 64*192*2 + 1024)   // ~198656

template <int NCOL, int MODE>
__device__ __forceinline__ void gemm_store(int row, int col, float val,
                                           float* out0, float* out1) {
    int b = row / NT, nn = row - b * NT;
    if (MODE == 0) {
        int p   = col / 192;
        int rem = col - p * 192;
        int h   = rem >> 5;
        int d   = rem & 31;
        float* dst = p ? out1 : out0;
        dst[((size_t)(b * H_ + h) * NT + nn) * DH + d] = val;
    } else {
        out0[(size_t)row * NCOL + col] = val;
    }
}

#if HAS_TCGEN05
__device__ __forceinline__ void stage_w(char* alg, int buf,
                                        const __nv_bfloat16* Wh,
                                        const __nv_bfloat16* Wl,
                                        int n0, int tid) {
    const __nv_bfloat16* wh = Wh + (size_t)n0 * 192;
    const __nv_bfloat16* wl = Wl + (size_t)n0 * 192;
    for (int id = tid; id < 64 * 24; id += 256) {
        int row = id / 24;
        int col = (id - row * 24) * 8;
        uint32_t off = (uint32_t)(((row >> 3) + (col >> 6) * 8) * 1024 +
                                  (row & 7) * 128 + (col & 63) * 2);
        uint32_t sw = SWZ(off);
        *(uint4*)(alg + OFF_W(buf, 0) + sw) = *(const uint4*)(wh + (size_t)row * 192 + col);
        *(uint4*)(alg + OFF_W(buf, 1) + sw) = *(const uint4*)(wl + (size_t)row * 192 + col);
    }
}

__device__ __forceinline__ void issue_mma_block(uint32_t base, uint32_t tmem_d,
                                                int buf) {
    uint64_t dAh = mk_desc(base + OFF_AH);
    uint64_t dAl = mk_desc(base + OFF_AL);
    uint64_t dWh = mk_desc(base + OFF_W(buf, 0));
    uint64_t dWl = mk_desc(base + OFF_W(buf, 1));
    uint64_t aB[3] = {dAh, dAl, dAh};
    uint64_t bB[3] = {dWh, dWh, dWl};
    #pragma unroll
    for (int t = 0; t < 3; t++) {
        #pragma unroll
        for (int s = 0; s < 12; s++) {
            uint64_t ad = aB[t] + (uint64_t)((s >> 2) * 1024 + (s & 3) * 2);
            uint64_t bd = bB[t] + (uint64_t)((s >> 2) * 512  + (s & 3) * 2);
            mma_f16_ss(tmem_d, ad, bd, IDESC, (t | s) != 0);
        }
    }
    TC_COMMIT(base + 8);
}
#endif

template <int NCOL, int MODE>
__global__ __launch_bounds__(256, 1)
void mma_gemm_kernel(const float* __restrict__ A,
                     const __nv_bfloat16* __restrict__ Wh,
                     const __nv_bfloat16* __restrict__ Wl,
                     const float* __restrict__ bias,
                     float* __restrict__ out0,
                     float* __restrict__ out1) {
#if HAS_TCGEN05
    constexpr int NB = NCOL / 64;
    extern __shared__ char smx[];
    const uint32_t raw = smem_u32(smx);
    const uint32_t base = (raw + 1023) & ~1023u;          // 1KB-aligned
    char* alg = smx + (base - raw);

    const int tid = threadIdx.x;
    const int wid = tid >> 5, lid = tid & 31;
    const int M0 = blockIdx.x * 128;

    if (wid == 0) {
        TC_ALLOC(base, 128);
        TC_RELINQ();
    }
    if (tid == 0) MBAR_INIT(base + 8, 1);

    // ---- stage A tile once: fp32 -> (hi, lo) bf16, SW128 blocked atoms ----
    for (int id = tid; id < 128 * 48; id += 256) {
        int row = id / 48;
        int col = (id - row * 48) * 4;
        float4 a = *(const float4*)(A + (size_t)(M0 + row) * 192 + col);
        unsigned short h0,h1,h2,h3,l0,l1,l2,l3;
        bsplit(a.x, h0, l0); bsplit(a.y, h1, l1);
        bsplit(a.z, h2, l2); bsplit(a.w, h3, l3);
        uint32_t off = (uint32_t)(((row >> 3) + (col >> 6) * 16) * 1024 +
                                  (row & 7) * 128 + (col & 63) * 2);
        uint32_t sw = SWZ(off);
        *(uint2*)(alg + OFF_AH + sw) =
            make_uint2((uint32_t)h0 | ((uint32_t)h1 << 16),
                       (uint32_t)h2 | ((uint32_t)h3 << 16));
        *(uint2*)(alg + OFF_AL + sw) =
            make_uint2((uint32_t)l0 | ((uint32_t)l1 << 16),
                       (uint32_t)l2 | ((uint32_t)l3 << 16));
    }
    // ---- stage W block 0 ----
    stage_w(alg, 0, Wh, Wl, 0, tid);
    FENCE_ASYNC();
    __syncthreads();

    uint32_t tmem;
    asm volatile("ld.shared.b32 %0, [%1];" : "=r"(tmem) : "r"(base));

    // ---- issue MMA block 0 ----
    if (wid == 0 && elect_one())
        issue_mma_block(base, tmem + 0, 0);

    // ---- pipelined N-block loop ----
    for (int n = 0; n < NB; n++) {
        if (n + 1 < NB)
            stage_w(alg, (n + 1) & 1, Wh, Wl, (n + 1) * 64, tid);
        FENCE_ASYNC();
        __syncthreads();

        MBAR_WAIT(base + 8, n & 1);          // MMA block n done
        TC_FENCE_AFTER();

        if (n + 1 < NB && wid == 0 && elect_one())
            issue_mma_block(base, tmem + ((n + 1) & 1) * 64, (n + 1) & 1);

        // epilogue block n: warps 0-3 read D[128,64] region (n&1)
        if (wid < 4) {
            uint32_t d0[32], d1[32];
            uint32_t td = tmem + (n & 1) * 64;
            TC_LD32X32(d0, td);
            TC_LD32X32(d1, td + 32);
            TC_WAIT_LD();
            int row = M0 + wid * 32 + lid;
            int N0 = n * 64;
            #pragma unroll
            for (int c = 0; c < 64; c++) {
                int col = N0 + c;
                float val = __uint_as_float(c < 32 ? d0[c] : d1[c - 32]) + bias[col];
                gemm_store<NCOL, MODE>(row, col, val, out0, out1);
            }
        }
    }

    __syncthreads();
    if (wid == 0) TC_DEALLOC(tmem, 128);

#else
    // ---------- SIMT fallback (compiled for non-a targets only) ----------
    const int tid = threadIdx.x;
    const int M0 = blockIdx.x * 128;
    int row = M0 + (tid >> 1);
    int half = (tid & 1);
    for (int nb = 0; nb < NCOL / 64; nb++) {
        int c0 = nb * 64 + half * 32;
        float acc[32];
        #pragma unroll
        for (int j = 0; j < 32; j++) acc[j] = 0.f;
        for (int k = 0; k < 192; k++) {
            float a = A[(size_t)row * 192 + k];
            #pragma unroll 8
            for (int j = 0; j < 32; j++) {
                float w = __bfloat162float(Wh[(size_t)(c0 + j) * 192 + k]) +
                          __bfloat162float(Wl[(size_t)(c0 + j) * 192 + k]);
                acc[j] += a * w;
            }
        }
        #pragma unroll
        for (int j = 0; j < 32; j++)
            gemm_store<NCOL, MODE>(row, c0 + j, acc[j] + bias[c0 + j], out0, out1);
    }
#endif
}

// ---------------------------------------------------------------------------
// Kernel 3: fused window attention (unchanged — known good)
// ---------------------------------------------------------------------------
__global__ __launch_bounds__(512, 1)
void attn_kernel(const float* __restrict__ xup,
                 const float* __restrict__ gk,
                 const float* __restrict__ gv,
                 const float* __restrict__ bias,
                 const float* __restrict__ mask,
                 float* __restrict__ xout) {
    extern __shared__ float sm[];
    float* ks = sm;                         // 344 * 33
    float* vs = ks + NTP * KS2;             // 344 * 33
    float* qs = vs + NTP * KS2;             // 16 * 128
    float* ps = qs + 16 * 128;              // 16 * 4 * 344

    const int tid = threadIdx.x;
    const int bh  = blockIdx.x;             // b*6 + h
    const int b   = bh / H_;
    const int h   = bh - b * H_;
    const int w   = b & (NWIN - 1);

    const float4* kg = (const float4*)(gk + (size_t)bh * NT * DH);
    const float4* vg = (const float4*)(gv + (size_t)bh * NT * DH);
    for (int idx = tid; idx < NT * 8; idx += 512) {
        int j = idx >> 3, c = (idx & 7) << 2;
        float4 a4 = kg[idx];
        float* kd = ks + j * KS2 + c;
        kd[0] = a4.x; kd[1] = a4.y; kd[2] = a4.z; kd[3] = a4.w;
        float4 b4 = vg[idx];
        float* vd = vs + j * KS2 + c;
        vd[0] = b4.x; vd[1] = b4.y; vd[2] = b4.z; vd[3] = b4.w;
    }
    if (tid < KS2) {
        ks[343 * KS2 + tid] = 0.f;
        vs[343 * KS2 + tid] = 0.f;
    }
    __syncthreads();

    const int warp = tid >> 5, lane = tid & 31;
    const float scale = 0.17677669529663687f;
    float* qw = qs + warp * 128;
    float* pw = ps + warp * 4 * NTP;
    const float* brow0 = bias + (size_t)h * NT * NT;
    const float* mrow0 = mask + (size_t)w * NT * NT;

    for (int it = 0; it < 6; it++) {
        const int row0 = it * 64 + warp * 4;

        #pragma unroll
        for (int rr = 0; rr < 4; rr++) {
            int row = min(row0 + rr, NT - 1);
            qw[rr * 32 + lane] =
                xup[((size_t)b * NT + row) * C_ + h * DH + lane] * scale;
        }
        __syncwarp();

        float acc[4][11];
        #pragma unroll
        for (int r = 0; r < 4; r++)
            #pragma unroll
            for (int tt = 0; tt < 11; tt++) acc[r][tt] = 0.f;

        #pragma unroll
        for (int dc = 0; dc < 32; dc += 8) {
            float qr[4][8];
            #pragma unroll
            for (int r = 0; r < 4; r++)
                #pragma unroll
                for (int dd = 0; dd < 8; dd++)
                    qr[r][dd] = qw[r * 32 + dc + dd];
            #pragma unroll
            for (int tt = 0; tt < 11; tt++) {
                int j  = tt * 32 + lane;
                int jc = min(j, NT);
                const float* kp = ks + jc * KS2 + dc;
                #pragma unroll
                for (int dd = 0; dd < 8; dd++) {
                    float kv = kp[dd];
                    #pragma unroll
                    for (int r = 0; r < 4; r++)
                        acc[r][tt] += qr[r][dd] * kv;
                }
            }
        }

        #pragma unroll
        for (int r = 0; r < 4; r++) {
            int row = min(row0 + r, NT - 1);
            const float* br = brow0 + (size_t)row * NT;
            const float* mr = mrow0 + (size_t)row * NT;
            float sreg[11];
            float mx = -1e30f;
            #pragma unroll
            for (int tt = 0; tt < 11; tt++) {
                int j = tt * 32 + lane;
                float s = -1e30f;
                if (j < NT) s = acc[r][tt] + br[j] + mr[j];
                sreg[tt] = s;
                mx = fmaxf(mx, s);
            }
            #pragma unroll
            for (int o = 16; o > 0; o >>= 1)
                mx = fmaxf(mx, __shfl_xor_sync(0xffffffffu, mx, o));
            float sum = 0.f;
            #pragma unroll
            for (int tt = 0; tt < 11; tt++) {
                float e = __expf(sreg[tt] - mx);
                sreg[tt] = e;
                sum += e;
            }
            #pragma unroll
            for (int o = 16; o > 0; o >>= 1)
                sum += __shfl_xor_sync(0xffffffffu, sum, o);
            float inv = 1.f / sum;
            #pragma unroll
            for (int tt = 0; tt < 11; tt++) {
                int j = tt * 32 + lane;
                if (j < NT) pw[r * NTP + j] = sreg[tt] * inv;
            }
            if (lane == 0) pw[r * NTP + NT] = 0.f;
        }
        __syncwarp();

        float o0 = 0.f, o1 = 0.f, o2 = 0.f, o3 = 0.f;
        #pragma unroll 2
        for (int j4 = 0; j4 < NTP; j4 += 4) {
            float vv0 = vs[(j4 + 0) * KS2 + lane];
            float vv1 = vs[(j4 + 1) * KS2 + lane];
            float vv2 = vs[(j4 + 2) * KS2 + lane];
            float vv3 = vs[(j4 + 3) * KS2 + lane];
            float4 p0 = *(const float4*)&pw[0 * NTP + j4];
            float4 p1 = *(const float4*)&pw[1 * NTP + j4];
            float4 p2 = *(const float4*)&pw[2 * NTP + j4];
            float4 p3 = *(const float4*)&pw[3 * NTP + j4];
            o0 += p0.x * vv0 + p0.y * vv1 + p0.z * vv2 + p0.w * vv3;
            o1 += p1.x * vv0 + p1.y * vv1 + p1.z * vv2 + p1.w * vv3;
            o2 += p2.x * vv0 + p2.y * vv1 + p2.z * vv2 + p2.w * vv3;
            o3 += p3.x * vv0 + p3.y * vv1 + p3.z * vv2 + p3.w * vv3;
        }

        float ov[4] = {o0, o1, o2, o3};
        #pragma unroll
        for (int r = 0; r < 4; r++) {
            int row = row0 + r;
            if (row < NT)
                xout[((size_t)b * NT + row) * C_ + h * DH + lane] = ov[r];
        }
        __syncwarp();
    }
}

// ---------------------------------------------------------------------------
extern "C" void kernel_launch(void* const* d_in, const int* in_sizes, int n_in,
                              void* d_out, int out_size) {
    const float* skip   = (const float*)d_in[0];
    const float* x_up   = (const float*)d_in[1];
    const float* mask   = (const float*)d_in[2];
    const int*   rel    = (const int*)d_in[3];
    const float* table  = (const float*)d_in[4];
    const float* kv_w   = (const float*)d_in[5];
    const float* kv_b   = (const float*)d_in[6];
    const float* proj_w = (const float*)d_in[7];
    const float* proj_b = (const float*)d_in[8];
    float* out = (float*)d_out;

    float *kptr, *vptr, *xptr, *biasptr;
    __nv_bfloat16 *whp, *wlp, *php, *plp;
    cudaGetSymbolAddress((void**)&kptr, g_k);
    cudaGetSymbolAddress((void**)&vptr, g_v);
    cudaGetSymbolAddress((void**)&xptr, g_x);
    cudaGetSymbolAddress((void**)&biasptr, g_bias);
    cudaGetSymbolAddress((void**)&whp, g_wh);
    cudaGetSymbolAddress((void**)&wlp, g_wl);
    cudaGetSymbolAddress((void**)&php, g_ph);
    cudaGetSymbolAddress((void**)&plp, g_pl);

    // 0. weight transpose + split
    wconv_kernel<<<(384 * 192 + 255) / 256, 256>>>(kv_w, 384, whp, wlp);
    wconv_kernel<<<(192 * 192 + 255) / 256, 256>>>(proj_w, 192, php, plp);

    // 1. bias gather
    bias_gather_kernel<<<(NT * NT + 255) / 256, 256>>>(rel, table, biasptr);

    // 2. kv projection (tcgen05, N-looped, scatter to g_k/g_v)
    cudaFuncSetAttribute(mma_gemm_kernel<384, 0>,
                         cudaFuncAttributeMaxDynamicSharedMemorySize, SMEM_GEMM);
    mma_gemm_kernel<384, 0><<<M_ / 128, 256, SMEM_GEMM>>>(
        skip, whp, wlp, kv_b, kptr, vptr);

    // 3. fused attention
    const int SMEM_ATTN = (2 * NTP * KS2 + 16 * 128 + 16 * 4 * NTP) * (int)sizeof(float);
    cudaFuncSetAttribute(attn_kernel, cudaFuncAttributeMaxDynamicSharedMemorySize, SMEM_ATTN);
    attn_kernel<<<B_ * H_, 512, SMEM_ATTN>>>(x_up, kptr, vptr, biasptr, mask, xptr);

    // 4. output projection (tcgen05) straight to d_out
    cudaFuncSetAttribute(mma_gemm_kernel<192, 1>,
                         cudaFuncAttributeMaxDynamicSharedMemorySize, SMEM_GEMM);
    mma_gemm_kernel<192, 1><<<M_ / 128, 256, SMEM_GEMM>>>(
        xptr, php, plp, proj_b, out, nullptr);
}